// round 7
// baseline (speedup 1.0000x reference)
#include <cuda_runtime.h>
#include <cuda_bf16.h>
#include <math.h>
#include <stdint.h>

#define BB 256
#define LL 256
#define DD 128
#define HH 2
#define EE 64
#define MROWS (BB*LL)     // 65536
#define KTOP 5
#define NTOT 100000

// ---------------- scratch (static device globals; no allocation) ----------------
static __device__ float g_x  [MROWS*DD];
static __device__ float g_v  [MROWS*DD];
static __device__ float g_sp [MROWS*DD];
static __device__ float g_mv [BB*LL];
static __device__ int   g_delays[KTOP];
static __device__ float g_w  [BB*KTOP];
static __device__ float g_hf [2*LL];
// bf16 split pairs
static __device__ __nv_bfloat16 g_xbh [MROWS*DD],  g_xbl [MROWS*DD];
static __device__ __nv_bfloat16 g_xfbh[MROWS*DD],  g_xfbl[MROWS*DD];
static __device__ __nv_bfloat16 g_qkbh[MROWS*384], g_qkbl[MROWS*384];
static __device__ __nv_bfloat16 g_abh [MROWS*DD],  g_abl [MROWS*DD];
static __device__ __nv_bfloat16 g_hbh [MROWS*2*DD],g_hbl [MROWS*2*DD];
static __device__ __nv_bfloat16 g_aobh[MROWS*DD],  g_aobl[MROWS*DD];
static __device__ __nv_bfloat16 g_Cbh [2*LL*LL],   g_Cbl [2*LL*LL];
static __device__ __nv_bfloat16 g_wTbh[262144],    g_wTbl[262144];

// ============================ helpers ============================
__device__ __forceinline__ uint32_t s2u(const void* p){
    uint32_t a;
    asm("{ .reg .u64 t; cvta.to.shared.u64 t, %1; cvt.u32.u64 %0, t; }" : "=r"(a) : "l"(p));
    return a;
}
__device__ __forceinline__ void ldm_x4(uint32_t& r0,uint32_t& r1,uint32_t& r2,uint32_t& r3,uint32_t addr){
    asm volatile("ldmatrix.sync.aligned.m8n8.x4.shared.b16 {%0,%1,%2,%3}, [%4];"
        : "=r"(r0),"=r"(r1),"=r"(r2),"=r"(r3) : "r"(addr));
}
__device__ __forceinline__ void mma16816(float* c, const uint32_t* a, const uint32_t* b){
    asm volatile("mma.sync.aligned.m16n8k16.row.col.f32.bf16.bf16.f32 "
        "{%0,%1,%2,%3}, {%4,%5,%6,%7}, {%8,%9}, {%0,%1,%2,%3};"
        : "+f"(c[0]),"+f"(c[1]),"+f"(c[2]),"+f"(c[3])
        : "r"(a[0]),"r"(a[1]),"r"(a[2]),"r"(a[3]), "r"(b[0]),"r"(b[1]));
}
__device__ __forceinline__ void bfsplit(float v, __nv_bfloat16& hi, __nv_bfloat16& lo){
    hi = __float2bfloat16_rn(v);
    lo = __float2bfloat16_rn(v - __bfloat162float(hi));
}

// ======= bf16-split tensor GEMM: C(128,64-tile) = act(A@B^T [+R]) =======
// A,B pre-split bf16 pairs. btrans=1: B(n,k)=B[k*ldb+n]. out: fp32 Cf and/or split Ch/Cl.
#define PIT 40
__global__ void __launch_bounds__(256) gemm_bf(
    const __nv_bfloat16* __restrict__ Ah_, const __nv_bfloat16* __restrict__ Al_, int lda, long sA,
    const __nv_bfloat16* __restrict__ Bh_, const __nv_bfloat16* __restrict__ Bl_, int ldb, long sB, int btrans,
    float* __restrict__ Cf, __nv_bfloat16* __restrict__ Ch_, __nv_bfloat16* __restrict__ Cl_,
    int ldc, long sC, const float* __restrict__ R, int K, int act)
{
    __shared__ __nv_bfloat16 Ahs[128*PIT], Als[128*PIT], Bhs[64*PIT], Bls[64*PIT];
    int tid = threadIdx.x, lane = tid & 31, warp = tid >> 5;
    int wm = warp & 3, wn = warp >> 2;
    int bm = blockIdx.x*128, bn = blockIdx.y*64, z = blockIdx.z;
    Ah_ += (size_t)z*sA; Al_ += (size_t)z*sA;
    Bh_ += (size_t)z*sB; Bl_ += (size_t)z*sB;
    if (Cf) Cf += (size_t)z*sC;
    if (Ch_){ Ch_ += (size_t)z*sC; Cl_ += (size_t)z*sC; }

    float c[2][4][4] = {};
    uint32_t sAh = s2u(Ahs), sAl = s2u(Als), sBh = s2u(Bhs), sBl = s2u(Bls);
    int a_row = (lane & 7) + ((lane >> 3) & 1)*8;
    int a_koff = (lane >> 4)*8;
    int b_nsel = lane >> 4;
    int b_row  = lane & 7;
    int b_koff = ((lane >> 3) & 1)*8;
    int ar = tid >> 1, aq = (tid & 1)*16;
    int br2 = tid >> 2, bq2 = (tid & 3)*8;
    int bn2 = tid & 63, bk0 = (tid >> 6)*8;

    for (int kc = 0; kc < K; kc += 32){
        {
            const __nv_bfloat16* pah = Ah_ + (size_t)(bm+ar)*lda + kc + aq;
            const __nv_bfloat16* pal = Al_ + (size_t)(bm+ar)*lda + kc + aq;
            *(uint4*)&Ahs[ar*PIT+aq]   = *(const uint4*)pah;
            *(uint4*)&Ahs[ar*PIT+aq+8] = *(const uint4*)(pah+8);
            *(uint4*)&Als[ar*PIT+aq]   = *(const uint4*)pal;
            *(uint4*)&Als[ar*PIT+aq+8] = *(const uint4*)(pal+8);
        }
        if (!btrans){
            *(uint4*)&Bhs[br2*PIT+bq2] = *(const uint4*)&Bh_[(size_t)(bn+br2)*ldb + kc + bq2];
            *(uint4*)&Bls[br2*PIT+bq2] = *(const uint4*)&Bl_[(size_t)(bn+br2)*ldb + kc + bq2];
        } else {
            #pragma unroll
            for (int j = 0; j < 8; j++){
                size_t src = (size_t)(kc + bk0 + j)*ldb + bn + bn2;
                Bhs[bn2*PIT + bk0 + j] = Bh_[src];
                Bls[bn2*PIT + bk0 + j] = Bl_[src];
            }
        }
        __syncthreads();

        #pragma unroll
        for (int ks = 0; ks < 2; ks++){
            int kb = ks*16;
            uint32_t ah[2][4], al[2][4], bh[4][2], bl[4][2];
            #pragma unroll
            for (int mt = 0; mt < 2; mt++){
                uint32_t off = (uint32_t)((wm*32 + mt*16 + a_row)*PIT + kb + a_koff)*2;
                ldm_x4(ah[mt][0], ah[mt][1], ah[mt][2], ah[mt][3], sAh + off);
                ldm_x4(al[mt][0], al[mt][1], al[mt][2], al[mt][3], sAl + off);
            }
            #pragma unroll
            for (int np = 0; np < 2; np++){
                uint32_t off = (uint32_t)((wn*32 + np*16 + b_nsel*8 + b_row)*PIT + kb + b_koff)*2;
                ldm_x4(bh[2*np][0], bh[2*np][1], bh[2*np+1][0], bh[2*np+1][1], sBh + off);
                ldm_x4(bl[2*np][0], bl[2*np][1], bl[2*np+1][0], bl[2*np+1][1], sBl + off);
            }
            #pragma unroll
            for (int mt = 0; mt < 2; mt++)
                #pragma unroll
                for (int nt = 0; nt < 4; nt++){
                    mma16816(c[mt][nt], ah[mt], bh[nt]);
                    mma16816(c[mt][nt], ah[mt], bl[nt]);
                    mma16816(c[mt][nt], al[mt], bh[nt]);
                }
        }
        __syncthreads();
    }

    int r0 = lane >> 2, c0 = (lane & 3)*2;
    #pragma unroll
    for (int mt = 0; mt < 2; mt++)
        #pragma unroll
        for (int nt = 0; nt < 4; nt++)
            #pragma unroll
            for (int half = 0; half < 2; half++){
                size_t row = (size_t)(bm + wm*32 + mt*16 + r0 + half*8);
                int col = bn + wn*32 + nt*8 + c0;
                float v0 = c[mt][nt][half*2+0], v1 = c[mt][nt][half*2+1];
                if (act == 1){
                    v0 += R[row*ldc + col]; v1 += R[row*ldc + col + 1];
                } else if (act == 2){
                    v0 = 0.5f*v0*(1.0f + erff(v0*0.70710678118654752f));
                    v1 = 0.5f*v1*(1.0f + erff(v1*0.70710678118654752f));
                }
                if (Cf) *(float2*)&Cf[row*ldc + col] = make_float2(v0, v1);
                if (Ch_){
                    __nv_bfloat16 h0,l0,h1,l1;
                    bfsplit(v0,h0,l0); bfsplit(v1,h1,l1);
                    *(__nv_bfloat162*)&Ch_[row*ldc + col] = __nv_bfloat162(h0,h1);
                    *(__nv_bfloat162*)&Cl_[row*ldc + col] = __nv_bfloat162(l0,l1);
                }
            }
}

// ======= fused attention: S once (+mv), softmax, P@Vt -> g_sp =======
// smem: [0,102400) Qh/Ql/Kh/Kl (PQ=80), overlapped by Ssm 64x260 f32 [0,66560)
// [102400,122880) Ph/Pl/Vh/Vl (PIT=40); [122880) msk; [123904) invs; [124160) mvs
#define PQ 80
#define SPIT 260
#define BSMEM 125184
__global__ void __launch_bounds__(256) attn_fused(const int* __restrict__ paths){
    extern __shared__ char smraw[];
    __nv_bfloat16* Qh = (__nv_bfloat16*)smraw;          // 64 x 80
    __nv_bfloat16* Ql = Qh + 64*PQ;
    __nv_bfloat16* Kh = Ql + 64*PQ;                     // 256 x 80
    __nv_bfloat16* Kl = Kh + 256*PQ;
    float* Ssm = (float*)smraw;                          // overlaps (phase 2)
    __nv_bfloat16* Ph = (__nv_bfloat16*)(smraw + 102400);
    __nv_bfloat16* Pl = Ph + 64*PIT;
    __nv_bfloat16* Vh = Pl + 64*PIT;
    __nv_bfloat16* Vl = Vh + 64*PIT;
    float* msk  = (float*)(smraw + 122880);
    float* invs = (float*)(smraw + 123904);
    float* mvs  = (float*)(smraw + 124160);
    int tid = threadIdx.x, lane = tid & 31, warp = tid >> 5;
    int bh = blockIdx.y, b = bh >> 1, h = bh & 1;
    int t0 = blockIdx.x*64;
    msk[tid] = (paths[b*LL + tid] < NTOT) ? 0.f : -10000.f;
    mvs[tid] = 0.f;
    // ---- load Q (64x64) and K (256x64) bf16 pairs ----
    {
        int r = tid >> 2, cq = (tid & 3)*16;
        size_t src = (size_t)(b*LL + t0 + r)*384 + h*EE + cq;
        *(uint4*)&Qh[r*PQ+cq]   = *(const uint4*)&g_qkbh[src];
        *(uint4*)&Qh[r*PQ+cq+8] = *(const uint4*)&g_qkbh[src+8];
        *(uint4*)&Ql[r*PQ+cq]   = *(const uint4*)&g_qkbl[src];
        *(uint4*)&Ql[r*PQ+cq+8] = *(const uint4*)&g_qkbl[src+8];
    }
    {
        int r = tid;
        size_t src = (size_t)(b*LL + r)*384 + 128 + h*EE;
        #pragma unroll
        for (int cq = 0; cq < 64; cq += 8){
            *(uint4*)&Kh[r*PQ+cq] = *(const uint4*)&g_qkbh[src+cq];
            *(uint4*)&Kl[r*PQ+cq] = *(const uint4*)&g_qkbl[src+cq];
        }
    }
    __syncthreads();
    int a_row = (lane & 7) + ((lane >> 3) & 1)*8, a_koff = (lane >> 4)*8;
    int b_nsel = lane >> 4, b_row = lane & 7, b_koff = ((lane >> 3) & 1)*8;
    // ---- phase 1: S = Qt @ Kt^T ----
    {
        int wm = warp & 1, wn = warp >> 1;
        uint32_t sQh = s2u(Qh), sQl = s2u(Ql), sKh = s2u(Kh), sKl = s2u(Kl);
        float cS[2][8][4] = {};
        #pragma unroll
        for (int kb = 0; kb < 64; kb += 16){
            uint32_t ah[2][4], al[2][4], bhf[8][2], blf[8][2];
            #pragma unroll
            for (int mt = 0; mt < 2; mt++){
                uint32_t off = (uint32_t)((wm*32 + mt*16 + a_row)*PQ + kb + a_koff)*2;
                ldm_x4(ah[mt][0],ah[mt][1],ah[mt][2],ah[mt][3], sQh + off);
                ldm_x4(al[mt][0],al[mt][1],al[mt][2],al[mt][3], sQl + off);
            }
            #pragma unroll
            for (int np = 0; np < 4; np++){
                uint32_t off = (uint32_t)((wn*64 + np*16 + b_nsel*8 + b_row)*PQ + kb + b_koff)*2;
                ldm_x4(bhf[2*np][0],bhf[2*np][1],bhf[2*np+1][0],bhf[2*np+1][1], sKh + off);
                ldm_x4(blf[2*np][0],blf[2*np][1],blf[2*np+1][0],blf[2*np+1][1], sKl + off);
            }
            #pragma unroll
            for (int mt = 0; mt < 2; mt++)
                #pragma unroll
                for (int nt = 0; nt < 8; nt++){
                    mma16816(cS[mt][nt], ah[mt], bhf[nt]);
                    mma16816(cS[mt][nt], ah[mt], blf[nt]);
                    mma16816(cS[mt][nt], al[mt], bhf[nt]);
                }
        }
        __syncthreads();   // Q/K reads done; Ssm may overwrite
        int rb = wm*32 + (lane >> 2);
        #pragma unroll
        for (int mt = 0; mt < 2; mt++)
            #pragma unroll
            for (int nt = 0; nt < 8; nt++)
                #pragma unroll
                for (int half = 0; half < 2; half++){
                    int row = rb + mt*16 + half*8;
                    int col = wn*64 + nt*8 + (lane & 3)*2;
                    float rv0 = cS[mt][nt][half*2+0], rv1 = cS[mt][nt][half*2+1];
                    // mean_value diag accumulation (raw S)
                    atomicAdd(&mvs[(t0 + row - col) & (LL-1)], rv0);
                    atomicAdd(&mvs[(t0 + row - col - 1) & (LL-1)], rv1);
                    *(float2*)&Ssm[row*SPIT + col] =
                        make_float2(rv0*0.125f + msk[col], rv1*0.125f + msk[col+1]);
                }
    }
    __syncthreads();
    atomicAdd(&g_mv[b*LL + tid], mvs[tid]*(1.0f/DD));
    // ---- softmax (4 threads per row) ----
    {
        int r = tid >> 2, q = tid & 3;
        float* Srow = Ssm + r*SPIT + q*64;
        float mx = -1e30f;
        #pragma unroll 16
        for (int c2 = 0; c2 < 64; c2++) mx = fmaxf(mx, Srow[c2]);
        mx = fmaxf(mx, __shfl_xor_sync(0xffffffffu, mx, 1));
        mx = fmaxf(mx, __shfl_xor_sync(0xffffffffu, mx, 2));
        float sum = 0.f;
        #pragma unroll 16
        for (int c2 = 0; c2 < 64; c2++){
            float e = expf(Srow[c2] - mx);
            Srow[c2] = e;
            sum += e;
        }
        sum += __shfl_xor_sync(0xffffffffu, sum, 1);
        sum += __shfl_xor_sync(0xffffffffu, sum, 2);
        if (q == 0) invs[r] = 1.0f/sum;
    }
    // ---- phase 2: P @ Vt ----
    int wmP = warp & 3, wnP = warp >> 2;
    uint32_t sPh = s2u(Ph), sPl = s2u(Pl), sVh = s2u(Vh), sVl = s2u(Vl);
    float cP[4][4] = {};
    for (int s0 = 0; s0 < LL; s0 += 32){
        __syncthreads();
        {
            int r = tid >> 2, q = tid & 3;
            #pragma unroll
            for (int j = 0; j < 8; j++){
                int sl = q*8 + j;
                __nv_bfloat16 hi, lo; bfsplit(Ssm[r*SPIT + s0 + sl], hi, lo);
                Ph[r*PIT + sl] = hi; Pl[r*PIT + sl] = lo;
            }
        }
        {
            int e = tid & 63, sj = tid >> 6;
            #pragma unroll
            for (int j = 0; j < 8; j++){
                int sl = sj*8 + j;
                size_t src = (size_t)(b*LL + s0 + sl)*384 + 256 + h*EE + e;
                Vh[e*PIT + sl] = g_qkbh[src];
                Vl[e*PIT + sl] = g_qkbl[src];
            }
        }
        __syncthreads();
        #pragma unroll
        for (int ks = 0; ks < 2; ks++){
            int kb = ks*16;
            uint32_t ah[4], al[4], bhf[4][2], blf[4][2];
            uint32_t offa = (uint32_t)((wmP*16 + a_row)*PIT + kb + a_koff)*2;
            ldm_x4(ah[0],ah[1],ah[2],ah[3], sPh + offa);
            ldm_x4(al[0],al[1],al[2],al[3], sPl + offa);
            #pragma unroll
            for (int np = 0; np < 2; np++){
                uint32_t off = (uint32_t)((wnP*32 + np*16 + b_nsel*8 + b_row)*PIT + kb + b_koff)*2;
                ldm_x4(bhf[2*np][0],bhf[2*np][1],bhf[2*np+1][0],bhf[2*np+1][1], sVh + off);
                ldm_x4(blf[2*np][0],blf[2*np][1],blf[2*np+1][0],blf[2*np+1][1], sVl + off);
            }
            #pragma unroll
            for (int nt = 0; nt < 4; nt++){
                mma16816(cP[nt], ah, bhf[nt]);
                mma16816(cP[nt], ah, blf[nt]);
                mma16816(cP[nt], al, bhf[nt]);
            }
        }
    }
    // ---- write spatial ----
    int rl = wmP*16 + (lane >> 2);
    #pragma unroll
    for (int nt = 0; nt < 4; nt++)
        #pragma unroll
        for (int half = 0; half < 2; half++){
            int row_l = rl + half*8;
            int t = t0 + row_l;
            float inv = invs[row_l];
            int col = wnP*32 + nt*8 + (lane & 3)*2;
            *(float2*)&g_sp[(size_t)(b*LL + t)*DD + h*EE + col] =
                make_float2(cP[nt][half*2+0]*inv, cP[nt][half*2+1]*inv);
        }
}

// ---------------- combine: ao = split(0.9*freq + 0.1*spatial) ----------------
__global__ void combine_k(){
    int bt = blockIdx.x; int b = bt >> 8; int t = bt & (LL-1);
    int d = threadIdx.x;
    int d5[KTOP]; float w5[KTOP];
    #pragma unroll
    for (int j = 0; j < KTOP; j++){ d5[j] = g_delays[j]; w5[j] = g_w[b*KTOP + j]; }
    float fr = 0.f;
    #pragma unroll
    for (int j = 0; j < KTOP; j++){
        int tt = (t + d5[j]) & (LL-1);
        fr += w5[j]*g_v[((size_t)b*LL + tt)*DD + d];
    }
    float o = 0.9f*fr + 0.1f*g_sp[(size_t)bt*DD + d];
    __nv_bfloat16 hi, lo; bfsplit(o, hi, lo);
    g_aobh[(size_t)bt*DD + d] = hi;
    g_aobl[(size_t)bt*DD + d] = lo;
}

// ---------------- weight transposes + split, one launch ----------------
__global__ void transp_all(const float* __restrict__ Wq, const float* __restrict__ Wk,
                           const float* __restrict__ Wv, const float* __restrict__ Wp,
                           const float* __restrict__ F1, const float* __restrict__ F2){
    int j = blockIdx.x, layer = j/6, idx = j%6;
    const float* src; int K, N, doff;
    switch(idx){
        case 0: src = Wq + layer*16384; K=128; N=128; doff=0; break;
        case 1: src = Wk + layer*16384; K=128; N=128; doff=16384; break;
        case 2: src = Wv + layer*16384; K=128; N=128; doff=32768; break;
        case 3: src = Wp + layer*16384; K=128; N=128; doff=49152; break;
        case 4: src = F1 + layer*32768; K=128; N=256; doff=65536; break;
        default: src = F2 + layer*32768; K=256; N=128; doff=98304; break;
    }
    doff += layer*131072;
    int total = K*N;
    int kmask = K - 1, kshift = (K == 128) ? 7 : 8;
    for (int e = blockIdx.y*blockDim.x + threadIdx.x; e < total; e += gridDim.y*blockDim.x){
        int kk = e & kmask, n = e >> kshift;
        __nv_bfloat16 hi, lo;
        bfsplit(src[(size_t)kk*N + n], hi, lo);
        g_wTbh[doff + e] = hi;
        g_wTbl[doff + e] = lo;
    }
}

// ---------------- embedding (fp32 + split) ----------------
__global__ void embed_k(const int* __restrict__ paths,
                        const float* __restrict__ ego,
                        const float* __restrict__ pos){
    int bt = blockIdx.x; int t = bt & (LL-1); int d = threadIdx.x;
    int p = paths[bt];
    float v = ego[(size_t)p*DD + d] + pos[t*DD + d];
    g_x[(size_t)bt*DD + d] = v;
    __nv_bfloat16 hi, lo; bfsplit(v, hi, lo);
    g_xbh[(size_t)bt*DD + d] = hi;
    g_xbl[(size_t)bt*DD + d] = lo;
}

// ---------------- band-pass filters + split circulant matrices ----------------
__global__ void filt2_k(){
    int layer = blockIdx.x, n = threadIdx.x;
    const int lefts[2]  = {51, 0};
    const int rights[2] = {129, 78};
    int l = lefts[layer], r = rights[layer];
    double s = 0.0;
    for (int f = l; f < r; f++){
        double w = (f == 0 || f == LL/2) ? 1.0 : 2.0;
        s += w * cos(6.283185307179586477 * (double)(f*n) / (double)LL);
    }
    g_hf[layer*LL + n] = (float)(s / (double)LL);
}
__global__ void buildC2_k(){
    int layer = blockIdx.y, t = blockIdx.x, s = threadIdx.x;
    float v = g_hf[layer*LL + ((t - s) & (LL-1))];
    __nv_bfloat16 hi, lo; bfsplit(v, hi, lo);
    g_Cbh[layer*LL*LL + t*LL + s] = hi;
    g_Cbl[layer*LL*LL + t*LL + s] = lo;
}
__global__ void zero_mv_k(){
    g_mv[blockIdx.x*1024 + threadIdx.x] = 0.f;
}

// ---------------- top-5 delays + per-batch weights ----------------
__global__ void topk_k(){
    __shared__ float sc[LL];
    int tau = threadIdx.x;
    float a = 0.f;
    for (int b = 0; b < BB; b++) a += g_mv[b*LL + tau];
    sc[tau] = a * (1.0f/BB);
    __syncthreads();
    if (tau == 0){
        for (int j = 0; j < KTOP; j++){
            float best = -1e30f; int bi = 0;
            for (int i = 0; i < LL; i++) if (sc[i] > best){ best = sc[i]; bi = i; }
            g_delays[j] = bi;
            sc[bi] = -1e30f;
        }
    }
}
__global__ void weights_k(){
    int b = threadIdx.x;
    float v[KTOP]; float mx = -1e30f;
    #pragma unroll
    for (int j = 0; j < KTOP; j++){ v[j] = g_mv[b*LL + g_delays[j]]; mx = fmaxf(mx, v[j]); }
    float s = 0.f;
    #pragma unroll
    for (int j = 0; j < KTOP; j++){ v[j] = expf(v[j]-mx); s += v[j]; }
    #pragma unroll
    for (int j = 0; j < KTOP; j++) g_w[b*KTOP + j] = v[j]/s;
}

// ---------------- final gather ----------------
__global__ void gather_k(const int* __restrict__ lengths, float* __restrict__ out){
    int b = blockIdx.x, d = threadIdx.x;
    int t = lengths[b] - 1;
    out[b*DD + d] = g_x[((size_t)b*LL + t)*DD + d];
}

// =====================================================================
extern "C" void kernel_launch(void* const* d_in, const int* in_sizes, int n_in,
                              void* d_out, int out_size){
    (void)in_sizes; (void)n_in; (void)out_size;
    const int*   paths   = (const int*)  d_in[0];
    const int*   lengths = (const int*)  d_in[1];
    const float* ego     = (const float*)d_in[4];
    const float* pos     = (const float*)d_in[5];
    const float* Wq      = (const float*)d_in[6];
    const float* Wk      = (const float*)d_in[7];
    const float* Wv      = (const float*)d_in[8];
    const float* Wp      = (const float*)d_in[9];
    const float* F1      = (const float*)d_in[10];
    const float* F2      = (const float*)d_in[11];
    float* outp = (float*)d_out;

    static bool init_done = false;
    static float *px, *pv;
    static __nv_bfloat16 *pxbh,*pxbl,*pxfbh,*pxfbl,*pqkbh,*pqkbl,*pabh,*pabl,
                         *phbh,*phbl,*paobh,*paobl,*pCbh,*pCbl,*pwTbh,*pwTbl;
    if (!init_done){
        cudaFuncSetAttribute(attn_fused, cudaFuncAttributeMaxDynamicSharedMemorySize, BSMEM);
        cudaGetSymbolAddress((void**)&px,    g_x);
        cudaGetSymbolAddress((void**)&pv,    g_v);
        cudaGetSymbolAddress((void**)&pxbh,  g_xbh);  cudaGetSymbolAddress((void**)&pxbl,  g_xbl);
        cudaGetSymbolAddress((void**)&pxfbh, g_xfbh); cudaGetSymbolAddress((void**)&pxfbl, g_xfbl);
        cudaGetSymbolAddress((void**)&pqkbh, g_qkbh); cudaGetSymbolAddress((void**)&pqkbl, g_qkbl);
        cudaGetSymbolAddress((void**)&pabh,  g_abh);  cudaGetSymbolAddress((void**)&pabl,  g_abl);
        cudaGetSymbolAddress((void**)&phbh,  g_hbh);  cudaGetSymbolAddress((void**)&phbl,  g_hbl);
        cudaGetSymbolAddress((void**)&paobh, g_aobh); cudaGetSymbolAddress((void**)&paobl, g_aobl);
        cudaGetSymbolAddress((void**)&pCbh,  g_Cbh);  cudaGetSymbolAddress((void**)&pCbl,  g_Cbl);
        cudaGetSymbolAddress((void**)&pwTbh, g_wTbh); cudaGetSymbolAddress((void**)&pwTbl, g_wTbl);
        init_done = true;
    }

    embed_k<<<MROWS, DD>>>(paths, ego, pos);
    filt2_k<<<2, LL>>>();
    buildC2_k<<<dim3(LL,2), LL>>>();
    transp_all<<<dim3(12,8), 256>>>(Wq, Wk, Wv, Wp, F1, F2);

    for (int k = 0; k < 2; k++){
        __nv_bfloat16 *wh = pwTbh + (size_t)k*131072, *wl = pwTbl + (size_t)k*131072;
        // xf = C @ x  (A=C split, B=x split transposed-load)
        gemm_bf<<<dim3(2,2,BB), 256>>>(pCbh + (size_t)k*LL*LL, pCbl + (size_t)k*LL*LL, LL, 0,
                                       pxbh, pxbl, DD, (long)LL*DD, 1,
                                       nullptr, pxfbh, pxfbl, DD, (long)LL*DD, nullptr, LL, 0);
        // qkvt = xf @ [Wq|Wk|Wv]
        gemm_bf<<<dim3(512,6,1), 256>>>(pxfbh, pxfbl, DD, 0, wh, wl, DD, 0, 0,
                                        nullptr, pqkbh, pqkbl, 384, 0, nullptr, DD, 0);
        // v = x @ Wv  (fp32 out)
        gemm_bf<<<dim3(512,2,1), 256>>>(pxbh, pxbl, DD, 0, wh + 32768, wl + 32768, DD, 0, 0,
                                        pv, nullptr, nullptr, DD, 0, nullptr, DD, 0);
        zero_mv_k<<<64, 1024>>>();
        attn_fused<<<dim3(4, BB*HH), 256, BSMEM>>>(paths);
        topk_k<<<1, LL>>>();
        weights_k<<<1, BB>>>();
        combine_k<<<MROWS, DD>>>();
        // a = ao @ Wp + x  (split out)
        gemm_bf<<<dim3(512,2,1), 256>>>(paobh, paobl, DD, 0, wh + 49152, wl + 49152, DD, 0, 0,
                                        nullptr, pabh, pabl, DD, 0, px, DD, 1);
        // h = gelu(a @ F1) (split out)
        gemm_bf<<<dim3(512,4,1), 256>>>(pabh, pabl, DD, 0, wh + 65536, wl + 65536, DD, 0, 0,
                                        nullptr, phbh, phbl, 2*DD, 0, nullptr, DD, 2);
        // x = h @ F2  (fp32 + split out)
        gemm_bf<<<dim3(512,2,1), 256>>>(phbh, phbl, 2*DD, 0, wh + 98304, wl + 98304, 2*DD, 0, 0,
                                        px, pxbh, pxbl, DD, 0, nullptr, 2*DD, 0);
    }
    gather_k<<<BB, DD>>>(lengths, outp);
}

// round 8
// speedup vs baseline: 1.3421x; 1.3421x over previous
#include <cuda_runtime.h>
#include <cuda_bf16.h>
#include <math.h>
#include <stdint.h>

#define BB 256
#define LL 256
#define DD 128
#define HH 2
#define EE 64
#define MROWS (BB*LL)     // 65536
#define KTOP 5
#define NTOT 100000

// ---------------- scratch (static device globals; no allocation) ----------------
static __device__ float g_x   [MROWS*DD];
static __device__ float g_xf  [MROWS*DD];
static __device__ float g_qkvt[MROWS*384];      // packed qt|kt|vt
static __device__ float g_v   [MROWS*DD];
static __device__ float g_sp  [MROWS*DD];
static __device__ float g_ao  [MROWS*DD];
static __device__ float g_a   [MROWS*DD];
static __device__ float g_h   [MROWS*2*DD];
static __device__ float g_mv  [BB*LL];
static __device__ int   g_delays[KTOP];
static __device__ float g_w   [BB*KTOP];
static __device__ float g_hf  [2*LL];
static __device__ float g_C   [2*LL*LL];        // circulant matrices, both layers
static __device__ float g_wT  [262144];         // transposed weights, both layers

// ============================ mma helpers ============================
__device__ __forceinline__ uint32_t s2u(const void* p){
    uint32_t a;
    asm("{ .reg .u64 t; cvta.to.shared.u64 t, %1; cvt.u32.u64 %0, t; }" : "=r"(a) : "l"(p));
    return a;
}
__device__ __forceinline__ void ldm_x4(uint32_t& r0,uint32_t& r1,uint32_t& r2,uint32_t& r3,uint32_t addr){
    asm volatile("ldmatrix.sync.aligned.m8n8.x4.shared.b16 {%0,%1,%2,%3}, [%4];"
        : "=r"(r0),"=r"(r1),"=r"(r2),"=r"(r3) : "r"(addr));
}
__device__ __forceinline__ void mma16816(float* c, const uint32_t* a, const uint32_t* b){
    asm volatile("mma.sync.aligned.m16n8k16.row.col.f32.bf16.bf16.f32 "
        "{%0,%1,%2,%3}, {%4,%5,%6,%7}, {%8,%9}, {%0,%1,%2,%3};"
        : "+f"(c[0]),"+f"(c[1]),"+f"(c[2]),"+f"(c[3])
        : "r"(a[0]),"r"(a[1]),"r"(a[2]),"r"(a[3]), "r"(b[0]),"r"(b[1]));
}
__device__ __forceinline__ void bfsplit(float v, __nv_bfloat16& hi, __nv_bfloat16& lo){
    hi = __float2bfloat16_rn(v);
    lo = __float2bfloat16_rn(v - __bfloat162float(hi));
}

// ======= tensor-core GEMM: C(Mtile=128, Ntile=64) = act(A@B^T [+R]) =======
#define PIT 40   // bf16 pitch (80 bytes): conflict-free ldmatrix
__global__ void __launch_bounds__(256) gemm_mma(
    const float* __restrict__ A, int lda, long sA,
    const float* __restrict__ B, int ldb, long sB, int btrans,
    float* __restrict__ C, int ldc, long sC,
    const float* __restrict__ R, int K, int act)
{
    __shared__ __nv_bfloat16 Ah[128*PIT], Al[128*PIT], Bh[64*PIT], Bl[64*PIT];
    int tid = threadIdx.x, lane = tid & 31, warp = tid >> 5;
    int wm = warp & 3, wn = warp >> 2;
    int bm = blockIdx.x*128, bn = blockIdx.y*64, z = blockIdx.z;
    A += (size_t)z * sA; B += (size_t)z * sB; C += (size_t)z * sC;

    float c[2][4][4] = {};
    uint32_t sAh = s2u(Ah), sAl = s2u(Al), sBh = s2u(Bh), sBl = s2u(Bl);
    int a_row = (lane & 7) + ((lane >> 3) & 1)*8;
    int a_koff = (lane >> 4)*8;
    int b_nsel = lane >> 4;
    int b_row  = lane & 7;
    int b_koff = ((lane >> 3) & 1)*8;

    for (int kc = 0; kc < K; kc += 32){
        {
            int rr = tid >> 4, c2 = tid & 15;
            #pragma unroll
            for (int p = 0; p < 8; p++){
                int r = rr + p*16;
                float2 v = *(const float2*)&A[(size_t)(bm+r)*lda + kc + c2*2];
                __nv_bfloat16 h0,h1,l0,l1;
                bfsplit(v.x,h0,l0); bfsplit(v.y,h1,l1);
                *(__nv_bfloat162*)&Ah[r*PIT + c2*2] = __nv_bfloat162(h0, h1);
                *(__nv_bfloat162*)&Al[r*PIT + c2*2] = __nv_bfloat162(l0, l1);
            }
        }
        if (!btrans){
            int rr = tid >> 4, c2 = tid & 15;
            #pragma unroll
            for (int p = 0; p < 4; p++){
                int r = rr + p*16;
                float2 v = *(const float2*)&B[(size_t)(bn+r)*ldb + kc + c2*2];
                __nv_bfloat16 h0,h1,l0,l1;
                bfsplit(v.x,h0,l0); bfsplit(v.y,h1,l1);
                *(__nv_bfloat162*)&Bh[r*PIT + c2*2] = __nv_bfloat162(h0, h1);
                *(__nv_bfloat162*)&Bl[r*PIT + c2*2] = __nv_bfloat162(l0, l1);
            }
        } else {
            int n = tid & 63, k0 = (tid >> 6)*8;
            #pragma unroll
            for (int j = 0; j < 8; j++){
                float v = B[(size_t)(kc + k0 + j)*ldb + bn + n];
                __nv_bfloat16 h,l;
                bfsplit(v,h,l);
                Bh[n*PIT + k0 + j] = h;
                Bl[n*PIT + k0 + j] = l;
            }
        }
        __syncthreads();

        #pragma unroll
        for (int ks = 0; ks < 2; ks++){
            int kb = ks*16;
            uint32_t ah[2][4], al[2][4], bh[4][2], bl[4][2];
            #pragma unroll
            for (int mt = 0; mt < 2; mt++){
                uint32_t off = (uint32_t)((wm*32 + mt*16 + a_row)*PIT + kb + a_koff)*2;
                ldm_x4(ah[mt][0], ah[mt][1], ah[mt][2], ah[mt][3], sAh + off);
                ldm_x4(al[mt][0], al[mt][1], al[mt][2], al[mt][3], sAl + off);
            }
            #pragma unroll
            for (int np = 0; np < 2; np++){
                uint32_t off = (uint32_t)((wn*32 + np*16 + b_nsel*8 + b_row)*PIT + kb + b_koff)*2;
                ldm_x4(bh[2*np][0], bh[2*np][1], bh[2*np+1][0], bh[2*np+1][1], sBh + off);
                ldm_x4(bl[2*np][0], bl[2*np][1], bl[2*np+1][0], bl[2*np+1][1], sBl + off);
            }
            #pragma unroll
            for (int mt = 0; mt < 2; mt++)
                #pragma unroll
                for (int nt = 0; nt < 4; nt++){
                    mma16816(c[mt][nt], ah[mt], bh[nt]);
                    mma16816(c[mt][nt], ah[mt], bl[nt]);
                    mma16816(c[mt][nt], al[mt], bh[nt]);
                }
        }
        __syncthreads();
    }

    int r0 = lane >> 2, c0 = (lane & 3)*2;
    #pragma unroll
    for (int mt = 0; mt < 2; mt++)
        #pragma unroll
        for (int nt = 0; nt < 4; nt++)
            #pragma unroll
            for (int half = 0; half < 2; half++){
                size_t row = (size_t)(bm + wm*32 + mt*16 + r0 + half*8);
                int col = bn + wn*32 + nt*8 + c0;
                float v0 = c[mt][nt][half*2+0], v1 = c[mt][nt][half*2+1];
                if (act == 1){
                    v0 += R[row*ldc + col]; v1 += R[row*ldc + col + 1];
                } else if (act == 2){
                    v0 = 0.5f*v0*(1.0f + erff(v0*0.70710678118654752f));
                    v1 = 0.5f*v1*(1.0f + erff(v1*0.70710678118654752f));
                }
                *(float2*)&C[row*ldc + col] = make_float2(v0, v1);
            }
}

// ======= fused attention: S once (+mean_value), softmax, P@Vt -> g_sp =======
// smem: [0,92160) Qh/Ql/Kh/Kl (PQ=72), overlapped by Ssm 64x260 f32 [0,66560)
// [92160,112640) Ph/Pl/Vh/Vl (PIT=40); [112640) msk; [113664) invs; [113920) mvs
#define PQ 72
#define SPIT 260
#define BSMEM (92160 + 20480 + 1024 + 256 + 1024)
__global__ void __launch_bounds__(256) attn_tc(const int* __restrict__ paths){
    extern __shared__ char smraw[];
    __nv_bfloat16* Qh = (__nv_bfloat16*)smraw;
    __nv_bfloat16* Ql = Qh + 64*PQ;
    __nv_bfloat16* Kh = Ql + 64*PQ;
    __nv_bfloat16* Kl = Kh + 256*PQ;
    float* Ssm = (float*)smraw;                       // overlaps Q/K (phase 2)
    __nv_bfloat16* Ph = (__nv_bfloat16*)(smraw + 92160);
    __nv_bfloat16* Pl = Ph + 64*PIT;
    __nv_bfloat16* Vh = Pl + 64*PIT;
    __nv_bfloat16* Vl = Vh + 64*PIT;
    float* msk  = (float*)(smraw + 112640);
    float* invs = (float*)(smraw + 113664);
    float* mvs  = (float*)(smraw + 113920);
    int tid = threadIdx.x, lane = tid & 31, warp = tid >> 5;
    int bh = blockIdx.y, b = bh >> 1, h = bh & 1;
    int t0 = blockIdx.x*64;
    msk[tid] = (paths[b*LL + tid] < NTOT) ? 0.f : -10000.f;
    mvs[tid] = 0.f;
    int c2 = tid & 31, r0 = tid >> 5;
    const float* Qg = g_qkvt + (size_t)b*LL*384 + h*EE;
    const float* Kg = g_qkvt + (size_t)b*LL*384 + 128 + h*EE;
    #pragma unroll
    for (int p = 0; p < 8; p++){
        int r = p*8 + r0;
        float2 v = *(const float2*)&Qg[(size_t)(t0+r)*384 + c2*2];
        __nv_bfloat16 h0,h1,l0,l1; bfsplit(v.x,h0,l0); bfsplit(v.y,h1,l1);
        *(__nv_bfloat162*)&Qh[r*PQ + c2*2] = __nv_bfloat162(h0,h1);
        *(__nv_bfloat162*)&Ql[r*PQ + c2*2] = __nv_bfloat162(l0,l1);
    }
    #pragma unroll
    for (int p = 0; p < 32; p++){
        int r = p*8 + r0;
        float2 v = *(const float2*)&Kg[(size_t)r*384 + c2*2];
        __nv_bfloat16 h0,h1,l0,l1; bfsplit(v.x,h0,l0); bfsplit(v.y,h1,l1);
        *(__nv_bfloat162*)&Kh[r*PQ + c2*2] = __nv_bfloat162(h0,h1);
        *(__nv_bfloat162*)&Kl[r*PQ + c2*2] = __nv_bfloat162(l0,l1);
    }
    __syncthreads();
    int a_row = (lane & 7) + ((lane >> 3) & 1)*8, a_koff = (lane >> 4)*8;
    int b_nsel = lane >> 4, b_row = lane & 7, b_koff = ((lane >> 3) & 1)*8;
    // ---- phase 1: S tile = Qt @ Kt^T ----
    {
        int wm = warp & 1, wn = warp >> 1;
        uint32_t sQh = s2u(Qh), sQl = s2u(Ql), sKh = s2u(Kh), sKl = s2u(Kl);
        float cS[2][8][4] = {};
        #pragma unroll
        for (int kb = 0; kb < 64; kb += 16){
            uint32_t ah[2][4], al[2][4], bhf[8][2], blf[8][2];
            #pragma unroll
            for (int mt = 0; mt < 2; mt++){
                uint32_t off = (uint32_t)((wm*32 + mt*16 + a_row)*PQ + kb + a_koff)*2;
                ldm_x4(ah[mt][0],ah[mt][1],ah[mt][2],ah[mt][3], sQh + off);
                ldm_x4(al[mt][0],al[mt][1],al[mt][2],al[mt][3], sQl + off);
            }
            #pragma unroll
            for (int np = 0; np < 4; np++){
                uint32_t off = (uint32_t)((wn*64 + np*16 + b_nsel*8 + b_row)*PQ + kb + b_koff)*2;
                ldm_x4(bhf[2*np][0],bhf[2*np][1],bhf[2*np+1][0],bhf[2*np+1][1], sKh + off);
                ldm_x4(blf[2*np][0],blf[2*np][1],blf[2*np+1][0],blf[2*np+1][1], sKl + off);
            }
            #pragma unroll
            for (int mt = 0; mt < 2; mt++)
                #pragma unroll
                for (int nt = 0; nt < 8; nt++){
                    mma16816(cS[mt][nt], ah[mt], bhf[nt]);
                    mma16816(cS[mt][nt], ah[mt], blf[nt]);
                    mma16816(cS[mt][nt], al[mt], bhf[nt]);
                }
        }
        __syncthreads();   // Q/K reads done; Ssm may overwrite
        int rb = wm*32 + (lane >> 2);
        #pragma unroll
        for (int mt = 0; mt < 2; mt++)
            #pragma unroll
            for (int nt = 0; nt < 8; nt++)
                #pragma unroll
                for (int half = 0; half < 2; half++){
                    int row = rb + mt*16 + half*8;
                    int col = wn*64 + nt*8 + (lane & 3)*2;
                    float rv0 = cS[mt][nt][half*2+0], rv1 = cS[mt][nt][half*2+1];
                    atomicAdd(&mvs[(t0 + row - col) & (LL-1)], rv0);
                    atomicAdd(&mvs[(t0 + row - col - 1) & (LL-1)], rv1);
                    *(float2*)&Ssm[row*SPIT + col] =
                        make_float2(rv0*0.125f + msk[col], rv1*0.125f + msk[col+1]);
                }
    }
    __syncthreads();
    atomicAdd(&g_mv[b*LL + tid], mvs[tid]*(1.0f/DD));
    // ---- softmax rows (4 threads per row) ----
    {
        int r = tid >> 2, q = tid & 3;
        float* Srow = Ssm + r*SPIT + q*64;
        float mx = -1e30f;
        #pragma unroll 16
        for (int cc = 0; cc < 64; cc++) mx = fmaxf(mx, Srow[cc]);
        mx = fmaxf(mx, __shfl_xor_sync(0xffffffffu, mx, 1));
        mx = fmaxf(mx, __shfl_xor_sync(0xffffffffu, mx, 2));
        float sum = 0.f;
        #pragma unroll 16
        for (int cc = 0; cc < 64; cc++){
            float e = expf(Srow[cc] - mx);
            Srow[cc] = e;
            sum += e;
        }
        sum += __shfl_xor_sync(0xffffffffu, sum, 1);
        sum += __shfl_xor_sync(0xffffffffu, sum, 2);
        if (q == 0) invs[r] = 1.0f/sum;
    }
    // ---- phase 2: P @ Vt ----
    int wmP = warp & 3, wnP = warp >> 2;
    uint32_t sPh = s2u(Ph), sPl = s2u(Pl), sVh = s2u(Vh), sVl = s2u(Vl);
    float cP[4][4] = {};
    for (int s0 = 0; s0 < LL; s0 += 32){
        __syncthreads();
        {
            int r = tid >> 2, q = tid & 3;
            #pragma unroll
            for (int j = 0; j < 8; j++){
                int sl = q*8 + j;
                __nv_bfloat16 hi, lo; bfsplit(Ssm[r*SPIT + s0 + sl], hi, lo);
                Ph[r*PIT + sl] = hi; Pl[r*PIT + sl] = lo;
            }
        }
        {
            int e = tid & 63, sj = tid >> 6;
            #pragma unroll
            for (int j = 0; j < 8; j++){
                int sl = sj*8 + j;
                float v = g_qkvt[(size_t)(b*LL + s0 + sl)*384 + 256 + h*EE + e];
                __nv_bfloat16 hi, lo; bfsplit(v, hi, lo);
                Vh[e*PIT + sl] = hi; Vl[e*PIT + sl] = lo;
            }
        }
        __syncthreads();
        #pragma unroll
        for (int ks = 0; ks < 2; ks++){
            int kb = ks*16;
            uint32_t ah[4], al[4], bhf[4][2], blf[4][2];
            uint32_t offa = (uint32_t)((wmP*16 + a_row)*PIT + kb + a_koff)*2;
            ldm_x4(ah[0],ah[1],ah[2],ah[3], sPh + offa);
            ldm_x4(al[0],al[1],al[2],al[3], sPl + offa);
            #pragma unroll
            for (int np = 0; np < 2; np++){
                uint32_t off = (uint32_t)((wnP*32 + np*16 + b_nsel*8 + b_row)*PIT + kb + b_koff)*2;
                ldm_x4(bhf[2*np][0],bhf[2*np][1],bhf[2*np+1][0],bhf[2*np+1][1], sVh + off);
                ldm_x4(blf[2*np][0],blf[2*np][1],blf[2*np+1][0],blf[2*np+1][1], sVl + off);
            }
            #pragma unroll
            for (int nt = 0; nt < 4; nt++){
                mma16816(cP[nt], ah, bhf[nt]);
                mma16816(cP[nt], ah, blf[nt]);
                mma16816(cP[nt], al, bhf[nt]);
            }
        }
    }
    // ---- write spatial ----
    int rl = wmP*16 + (lane >> 2);
    #pragma unroll
    for (int nt = 0; nt < 4; nt++)
        #pragma unroll
        for (int half = 0; half < 2; half++){
            int row_l = rl + half*8;
            int t = t0 + row_l;
            float inv = invs[row_l];
            int col = wnP*32 + nt*8 + (lane & 3)*2;
            *(float2*)&g_sp[(size_t)(b*LL + t)*DD + h*EE + col] =
                make_float2(cP[nt][half*2+0]*inv, cP[nt][half*2+1]*inv);
        }
}

// ---------------- combine: ao = 0.9*freq + 0.1*spatial ----------------
__global__ void combine_k(){
    int bt = blockIdx.x; int b = bt >> 8; int t = bt & (LL-1);
    int d = threadIdx.x;
    int d5[KTOP]; float w5[KTOP];
    #pragma unroll
    for (int j = 0; j < KTOP; j++){ d5[j] = g_delays[j]; w5[j] = g_w[b*KTOP + j]; }
    float fr = 0.f;
    #pragma unroll
    for (int j = 0; j < KTOP; j++){
        int tt = (t + d5[j]) & (LL-1);
        fr += w5[j]*g_v[((size_t)b*LL + tt)*DD + d];
    }
    g_ao[(size_t)bt*DD + d] = 0.9f*fr + 0.1f*g_sp[(size_t)bt*DD + d];
}

// ---------------- all weight transposes, one launch (both layers) ----------------
__global__ void transp_all(const float* __restrict__ Wq, const float* __restrict__ Wk,
                           const float* __restrict__ Wv, const float* __restrict__ Wp,
                           const float* __restrict__ F1, const float* __restrict__ F2){
    int j = blockIdx.x, layer = j/6, idx = j%6;
    const float* src; int K, N, doff;
    switch(idx){
        case 0: src = Wq + layer*16384; K=128; N=128; doff=0; break;
        case 1: src = Wk + layer*16384; K=128; N=128; doff=16384; break;
        case 2: src = Wv + layer*16384; K=128; N=128; doff=32768; break;
        case 3: src = Wp + layer*16384; K=128; N=128; doff=49152; break;
        case 4: src = F1 + layer*32768; K=128; N=256; doff=65536; break;
        default: src = F2 + layer*32768; K=256; N=128; doff=98304; break;
    }
    doff += layer*131072;
    int total = K*N;
    int kmask = K - 1, kshift = (K == 128) ? 7 : 8;
    for (int e = blockIdx.y*blockDim.x + threadIdx.x; e < total; e += gridDim.y*blockDim.x){
        int kk = e & kmask, n = e >> kshift;
        g_wT[doff + e] = src[(size_t)kk*N + n];
    }
}

// ---------------- embedding ----------------
__global__ void embed_k(const int* __restrict__ paths,
                        const float* __restrict__ ego,
                        const float* __restrict__ pos){
    int bt = blockIdx.x; int t = bt & (LL-1); int d = threadIdx.x;
    int p = paths[bt];
    g_x[(size_t)bt*DD + d] = ego[(size_t)p*DD + d] + pos[t*DD + d];
}

// ---------------- band-pass impulse responses + circulant matrices ----------------
__global__ void filt2_k(){
    int layer = blockIdx.x, n = threadIdx.x;
    const int lefts[2]  = {51, 0};
    const int rights[2] = {129, 78};
    int l = lefts[layer], r = rights[layer];
    double s = 0.0;
    for (int f = l; f < r; f++){
        double w = (f == 0 || f == LL/2) ? 1.0 : 2.0;
        s += w * cos(6.283185307179586477 * (double)(f*n) / (double)LL);
    }
    g_hf[layer*LL + n] = (float)(s / (double)LL);
}
__global__ void buildC2_k(){
    int layer = blockIdx.y, t = blockIdx.x, s = threadIdx.x;
    g_C[layer*LL*LL + t*LL + s] = g_hf[layer*LL + ((t - s) & (LL-1))];
}
__global__ void zero_mv_k(){
    g_mv[blockIdx.x*1024 + threadIdx.x] = 0.f;
}

// ---------------- top-5 delays + per-batch weights ----------------
__global__ void topk_k(){
    __shared__ float sc[LL];
    int tau = threadIdx.x;
    float a = 0.f;
    for (int b = 0; b < BB; b++) a += g_mv[b*LL + tau];
    sc[tau] = a * (1.0f/BB);
    __syncthreads();
    if (tau == 0){
        for (int j = 0; j < KTOP; j++){
            float best = -1e30f; int bi = 0;
            for (int i = 0; i < LL; i++) if (sc[i] > best){ best = sc[i]; bi = i; }
            g_delays[j] = bi;
            sc[bi] = -1e30f;
        }
    }
}
__global__ void weights_k(){
    int b = threadIdx.x;
    float v[KTOP]; float mx = -1e30f;
    #pragma unroll
    for (int j = 0; j < KTOP; j++){ v[j] = g_mv[b*LL + g_delays[j]]; mx = fmaxf(mx, v[j]); }
    float s = 0.f;
    #pragma unroll
    for (int j = 0; j < KTOP; j++){ v[j] = expf(v[j]-mx); s += v[j]; }
    #pragma unroll
    for (int j = 0; j < KTOP; j++) g_w[b*KTOP + j] = v[j]/s;
}

// ---------------- final gather ----------------
__global__ void gather_k(const int* __restrict__ lengths, float* __restrict__ out){
    int b = blockIdx.x, d = threadIdx.x;
    int t = lengths[b] - 1;
    out[b*DD + d] = g_x[((size_t)b*LL + t)*DD + d];
}

// =====================================================================
extern "C" void kernel_launch(void* const* d_in, const int* in_sizes, int n_in,
                              void* d_out, int out_size){
    (void)in_sizes; (void)n_in; (void)out_size;
    const int*   paths   = (const int*)  d_in[0];
    const int*   lengths = (const int*)  d_in[1];
    const float* ego     = (const float*)d_in[4];
    const float* pos     = (const float*)d_in[5];
    const float* Wq      = (const float*)d_in[6];
    const float* Wk      = (const float*)d_in[7];
    const float* Wv      = (const float*)d_in[8];
    const float* Wp      = (const float*)d_in[9];
    const float* F1      = (const float*)d_in[10];
    const float* F2      = (const float*)d_in[11];
    float* outp = (float*)d_out;

    static bool init_done = false;
    static float *px, *pxf, *pqkvt, *pv, *pao, *pa, *ph, *pC, *pwT;
    if (!init_done){
        cudaFuncSetAttribute(attn_tc, cudaFuncAttributeMaxDynamicSharedMemorySize, BSMEM);
        cudaGetSymbolAddress((void**)&px,   g_x);
        cudaGetSymbolAddress((void**)&pxf,  g_xf);
        cudaGetSymbolAddress((void**)&pqkvt,g_qkvt);
        cudaGetSymbolAddress((void**)&pv,   g_v);
        cudaGetSymbolAddress((void**)&pao,  g_ao);
        cudaGetSymbolAddress((void**)&pa,   g_a);
        cudaGetSymbolAddress((void**)&ph,   g_h);
        cudaGetSymbolAddress((void**)&pC,   g_C);
        cudaGetSymbolAddress((void**)&pwT,  g_wT);
        init_done = true;
    }

    embed_k<<<MROWS, DD>>>(paths, ego, pos);
    filt2_k<<<2, LL>>>();
    buildC2_k<<<dim3(LL,2), LL>>>();
    transp_all<<<dim3(12,8), 256>>>(Wq, Wk, Wv, Wp, F1, F2);

    for (int k = 0; k < 2; k++){
        float* wTk = pwT + (size_t)k*131072;
        // xf = C @ x  (per batch; B = x with transposed load)
        gemm_mma<<<dim3(2,2,BB), 256>>>(pC + (size_t)k*LL*LL, LL, 0,  px, DD, (long)LL*DD, 1,
                                        pxf, DD, (long)LL*DD, nullptr, LL, 0);
        // qkvt = xf @ [Wq|Wk|Wv]
        gemm_mma<<<dim3(512,6,1), 256>>>(pxf, DD, 0,  wTk, DD, 0, 0,
                                         pqkvt, 384, 0, nullptr, DD, 0);
        // v = x @ Wv
        gemm_mma<<<dim3(512,2,1), 256>>>(px, DD, 0,  wTk + 32768, DD, 0, 0,
                                         pv, DD, 0, nullptr, DD, 0);
        zero_mv_k<<<64, 1024>>>();
        attn_tc<<<dim3(4, BB*HH), 256, BSMEM>>>(paths);       // S once + mv + softmax + P@Vt
        topk_k<<<1, LL>>>();
        weights_k<<<1, BB>>>();
        combine_k<<<MROWS, DD>>>();
        // a = ao @ Wp + x
        gemm_mma<<<dim3(512,2,1), 256>>>(pao, DD, 0,  wTk + 49152, DD, 0, 0,
                                         pa, DD, 0, px, DD, 1);
        // h = gelu(a @ F1)
        gemm_mma<<<dim3(512,4,1), 256>>>(pa, DD, 0,  wTk + 65536, DD, 0, 0,
                                         ph, 2*DD, 0, nullptr, DD, 2);
        // x = h @ F2
        gemm_mma<<<dim3(512,2,1), 256>>>(ph, 2*DD, 0,  wTk + 98304, 2*DD, 0, 0,
                                         px, DD, 0, nullptr, 2*DD, 0);
    }
    gather_k<<<BB, DD>>>(lengths, outp);
}

// round 10
// speedup vs baseline: 1.3660x; 1.0178x over previous
#include <cuda_runtime.h>
#include <cuda_bf16.h>
#include <math.h>
#include <stdint.h>

#define BB 256
#define LL 256
#define DD 128
#define HH 2
#define EE 64
#define MROWS (BB*LL)     // 65536
#define KTOP 5
#define NTOT 100000

// ---------------- scratch (static device globals; no allocation) ----------------
static __device__ float g_x   [MROWS*DD];
static __device__ float g_xf  [MROWS*DD];
static __device__ float g_qkvt[MROWS*384];      // packed qt|kt|vt
static __device__ float g_v   [MROWS*DD];
static __device__ float g_sp  [MROWS*DD];
static __device__ float g_ao  [MROWS*DD];
static __device__ float g_a   [MROWS*DD];
static __device__ float g_h   [MROWS*2*DD];
static __device__ float g_mv  [BB*LL];
static __device__ int   g_delays[KTOP];
static __device__ float g_w   [BB*KTOP];
static __device__ float g_hf  [2*LL];
// pre-split static operands (bf16 hi/lo pairs)
static __device__ __nv_bfloat16 g_Cbh [2*LL*LL], g_Cbl [2*LL*LL];
static __device__ __nv_bfloat16 g_wTbh[262144],  g_wTbl[262144];

// ============================ mma helpers ============================
__device__ __forceinline__ uint32_t s2u(const void* p){
    uint32_t a;
    asm("{ .reg .u64 t; cvta.to.shared.u64 t, %1; cvt.u32.u64 %0, t; }" : "=r"(a) : "l"(p));
    return a;
}
__device__ __forceinline__ void ldm_x4(uint32_t& r0,uint32_t& r1,uint32_t& r2,uint32_t& r3,uint32_t addr){
    asm volatile("ldmatrix.sync.aligned.m8n8.x4.shared.b16 {%0,%1,%2,%3}, [%4];"
        : "=r"(r0),"=r"(r1),"=r"(r2),"=r"(r3) : "r"(addr));
}
__device__ __forceinline__ void mma16816(float* c, const uint32_t* a, const uint32_t* b){
    asm volatile("mma.sync.aligned.m16n8k16.row.col.f32.bf16.bf16.f32 "
        "{%0,%1,%2,%3}, {%4,%5,%6,%7}, {%8,%9}, {%0,%1,%2,%3};"
        : "+f"(c[0]),"+f"(c[1]),"+f"(c[2]),"+f"(c[3])
        : "r"(a[0]),"r"(a[1]),"r"(a[2]),"r"(a[3]), "r"(b[0]),"r"(b[1]));
}
__device__ __forceinline__ void bfsplit(float v, __nv_bfloat16& hi, __nv_bfloat16& lo){
    hi = __float2bfloat16_rn(v);
    lo = __float2bfloat16_rn(v - __bfloat162float(hi));
}

// ======= tensor-core GEMM: C(Mtile=128, Ntile=64) = act(A@B^T [+R]) =======
// APRE=1: A is pre-split bf16 pair (Ap/Ap2). APRE=0: A fp32, split in-kernel.
// BTRANS=0: B pre-split bf16 pair (Bp/Bp2), row-major (N,K).
// BTRANS=1: B fp32, B(n,k)=B[k*ldb+n], split in-kernel.
#define PIT 40   // bf16 pitch (80 bytes): conflict-free ldmatrix
template<int APRE, int BTRANS>
__global__ void __launch_bounds__(256) gemm_mma(
    const void* __restrict__ Ap, const void* __restrict__ Ap2, int lda, long sA,
    const void* __restrict__ Bp, const void* __restrict__ Bp2, int ldb, long sB,
    float* __restrict__ C, int ldc, long sC,
    const float* __restrict__ R, int K, int act)
{
    __shared__ __nv_bfloat16 Ahs[128*PIT], Als[128*PIT], Bhs[64*PIT], Bls[64*PIT];
    int tid = threadIdx.x, lane = tid & 31, warp = tid >> 5;
    int wm = warp & 3, wn = warp >> 2;
    int bm = blockIdx.x*128, bn = blockIdx.y*64, z = blockIdx.z;
    C += (size_t)z * sC;

    float c[2][4][4] = {};
    uint32_t sAh = s2u(Ahs), sAl = s2u(Als), sBh = s2u(Bhs), sBl = s2u(Bls);
    int a_row = (lane & 7) + ((lane >> 3) & 1)*8;
    int a_koff = (lane >> 4)*8;
    int b_nsel = lane >> 4;
    int b_row  = lane & 7;
    int b_koff = ((lane >> 3) & 1)*8;

    for (int kc = 0; kc < K; kc += 32){
        // ---- A chunk: 128 rows x 32 k ----
        if (APRE){
            const __nv_bfloat16* Abh = (const __nv_bfloat16*)Ap  + (size_t)z*sA;
            const __nv_bfloat16* Abl = (const __nv_bfloat16*)Ap2 + (size_t)z*sA;
            int ar = tid >> 1, aq = (tid & 1)*16;
            size_t src = (size_t)(bm+ar)*lda + kc + aq;
            *(uint4*)&Ahs[ar*PIT+aq]   = *(const uint4*)&Abh[src];
            *(uint4*)&Ahs[ar*PIT+aq+8] = *(const uint4*)&Abh[src+8];
            *(uint4*)&Als[ar*PIT+aq]   = *(const uint4*)&Abl[src];
            *(uint4*)&Als[ar*PIT+aq+8] = *(const uint4*)&Abl[src+8];
        } else {
            const float* A = (const float*)Ap + (size_t)z*sA;
            int rr = tid >> 4, c2 = tid & 15;
            #pragma unroll
            for (int p = 0; p < 8; p++){
                int r = rr + p*16;
                float2 v = *(const float2*)&A[(size_t)(bm+r)*lda + kc + c2*2];
                __nv_bfloat16 h0,h1,l0,l1;
                bfsplit(v.x,h0,l0); bfsplit(v.y,h1,l1);
                *(__nv_bfloat162*)&Ahs[r*PIT + c2*2] = __nv_bfloat162(h0, h1);
                *(__nv_bfloat162*)&Als[r*PIT + c2*2] = __nv_bfloat162(l0, l1);
            }
        }
        // ---- B chunk: 64 n-rows x 32 k ----
        if (!BTRANS){
            const __nv_bfloat16* Bbh = (const __nv_bfloat16*)Bp  + (size_t)z*sB;
            const __nv_bfloat16* Bbl = (const __nv_bfloat16*)Bp2 + (size_t)z*sB;
            int br2 = tid >> 2, bq2 = (tid & 3)*8;
            size_t src = (size_t)(bn+br2)*ldb + kc + bq2;
            *(uint4*)&Bhs[br2*PIT+bq2] = *(const uint4*)&Bbh[src];
            *(uint4*)&Bls[br2*PIT+bq2] = *(const uint4*)&Bbl[src];
        } else {
            const float* B = (const float*)Bp + (size_t)z*sB;
            int n = tid & 63, k0 = (tid >> 6)*8;
            #pragma unroll
            for (int j = 0; j < 8; j++){
                float v = B[(size_t)(kc + k0 + j)*ldb + bn + n];
                __nv_bfloat16 h,l;
                bfsplit(v,h,l);
                Bhs[n*PIT + k0 + j] = h;
                Bls[n*PIT + k0 + j] = l;
            }
        }
        __syncthreads();

        #pragma unroll
        for (int ks = 0; ks < 2; ks++){
            int kb = ks*16;
            uint32_t ah[2][4], al[2][4], bh[4][2], bl[4][2];
            #pragma unroll
            for (int mt = 0; mt < 2; mt++){
                uint32_t off = (uint32_t)((wm*32 + mt*16 + a_row)*PIT + kb + a_koff)*2;
                ldm_x4(ah[mt][0], ah[mt][1], ah[mt][2], ah[mt][3], sAh + off);
                ldm_x4(al[mt][0], al[mt][1], al[mt][2], al[mt][3], sAl + off);
            }
            #pragma unroll
            for (int np = 0; np < 2; np++){
                uint32_t off = (uint32_t)((wn*32 + np*16 + b_nsel*8 + b_row)*PIT + kb + b_koff)*2;
                ldm_x4(bh[2*np][0], bh[2*np][1], bh[2*np+1][0], bh[2*np+1][1], sBh + off);
                ldm_x4(bl[2*np][0], bl[2*np][1], bl[2*np+1][0], bl[2*np+1][1], sBl + off);
            }
            #pragma unroll
            for (int mt = 0; mt < 2; mt++)
                #pragma unroll
                for (int nt = 0; nt < 4; nt++){
                    mma16816(c[mt][nt], ah[mt], bh[nt]);
                    mma16816(c[mt][nt], ah[mt], bl[nt]);
                    mma16816(c[mt][nt], al[mt], bh[nt]);
                }
        }
        __syncthreads();
    }

    int r0 = lane >> 2, c0 = (lane & 3)*2;
    #pragma unroll
    for (int mt = 0; mt < 2; mt++)
        #pragma unroll
        for (int nt = 0; nt < 4; nt++)
            #pragma unroll
            for (int half = 0; half < 2; half++){
                size_t row = (size_t)(bm + wm*32 + mt*16 + r0 + half*8);
                int col = bn + wn*32 + nt*8 + c0;
                float v0 = c[mt][nt][half*2+0], v1 = c[mt][nt][half*2+1];
                if (act == 1){
                    v0 += R[row*ldc + col]; v1 += R[row*ldc + col + 1];
                } else if (act == 2){
                    v0 = 0.5f*v0*(1.0f + erff(v0*0.70710678118654752f));
                    v1 = 0.5f*v1*(1.0f + erff(v1*0.70710678118654752f));
                }
                *(float2*)&C[row*ldc + col] = make_float2(v0, v1);
            }
}

// ======= fused attention: S once (+mean_value), softmax, P@Vt -> g_sp =======
#define PQ 72
#define SPIT 260
#define BSMEM (92160 + 20480 + 1024 + 256 + 1024)
__global__ void __launch_bounds__(256) attn_tc(const int* __restrict__ paths){
    extern __shared__ char smraw[];
    __nv_bfloat16* Qh = (__nv_bfloat16*)smraw;
    __nv_bfloat16* Ql = Qh + 64*PQ;
    __nv_bfloat16* Kh = Ql + 64*PQ;
    __nv_bfloat16* Kl = Kh + 256*PQ;
    float* Ssm = (float*)smraw;                       // overlaps Q/K (phase 2)
    __nv_bfloat16* Ph = (__nv_bfloat16*)(smraw + 92160);
    __nv_bfloat16* Pl = Ph + 64*PIT;
    __nv_bfloat16* Vh = Pl + 64*PIT;
    __nv_bfloat16* Vl = Vh + 64*PIT;
    float* msk  = (float*)(smraw + 112640);
    float* invs = (float*)(smraw + 113664);
    float* mvs  = (float*)(smraw + 113920);
    int tid = threadIdx.x, lane = tid & 31, warp = tid >> 5;
    int bh = blockIdx.y, b = bh >> 1, h = bh & 1;
    int t0 = blockIdx.x*64;
    msk[tid] = (paths[b*LL + tid] < NTOT) ? 0.f : -10000.f;
    mvs[tid] = 0.f;
    int c2 = tid & 31, r0 = tid >> 5;
    const float* Qg = g_qkvt + (size_t)b*LL*384 + h*EE;
    const float* Kg = g_qkvt + (size_t)b*LL*384 + 128 + h*EE;
    #pragma unroll
    for (int p = 0; p < 8; p++){
        int r = p*8 + r0;
        float2 v = *(const float2*)&Qg[(size_t)(t0+r)*384 + c2*2];
        __nv_bfloat16 h0,h1,l0,l1; bfsplit(v.x,h0,l0); bfsplit(v.y,h1,l1);
        *(__nv_bfloat162*)&Qh[r*PQ + c2*2] = __nv_bfloat162(h0,h1);
        *(__nv_bfloat162*)&Ql[r*PQ + c2*2] = __nv_bfloat162(l0,l1);
    }
    #pragma unroll
    for (int p = 0; p < 32; p++){
        int r = p*8 + r0;
        float2 v = *(const float2*)&Kg[(size_t)r*384 + c2*2];
        __nv_bfloat16 h0,h1,l0,l1; bfsplit(v.x,h0,l0); bfsplit(v.y,h1,l1);
        *(__nv_bfloat162*)&Kh[r*PQ + c2*2] = __nv_bfloat162(h0,h1);
        *(__nv_bfloat162*)&Kl[r*PQ + c2*2] = __nv_bfloat162(l0,l1);
    }
    __syncthreads();
    int a_row = (lane & 7) + ((lane >> 3) & 1)*8, a_koff = (lane >> 4)*8;
    int b_nsel = lane >> 4, b_row = lane & 7, b_koff = ((lane >> 3) & 1)*8;
    // ---- phase 1: S tile = Qt @ Kt^T ----
    {
        int wm = warp & 1, wn = warp >> 1;
        uint32_t sQh = s2u(Qh), sQl = s2u(Ql), sKh = s2u(Kh), sKl = s2u(Kl);
        float cS[2][8][4] = {};
        #pragma unroll
        for (int kb = 0; kb < 64; kb += 16){
            uint32_t ah[2][4], al[2][4], bhf[8][2], blf[8][2];
            #pragma unroll
            for (int mt = 0; mt < 2; mt++){
                uint32_t off = (uint32_t)((wm*32 + mt*16 + a_row)*PQ + kb + a_koff)*2;
                ldm_x4(ah[mt][0],ah[mt][1],ah[mt][2],ah[mt][3], sQh + off);
                ldm_x4(al[mt][0],al[mt][1],al[mt][2],al[mt][3], sQl + off);
            }
            #pragma unroll
            for (int np = 0; np < 4; np++){
                uint32_t off = (uint32_t)((wn*64 + np*16 + b_nsel*8 + b_row)*PQ + kb + b_koff)*2;
                ldm_x4(bhf[2*np][0],bhf[2*np][1],bhf[2*np+1][0],bhf[2*np+1][1], sKh + off);
                ldm_x4(blf[2*np][0],blf[2*np][1],blf[2*np+1][0],blf[2*np+1][1], sKl + off);
            }
            #pragma unroll
            for (int mt = 0; mt < 2; mt++)
                #pragma unroll
                for (int nt = 0; nt < 8; nt++){
                    mma16816(cS[mt][nt], ah[mt], bhf[nt]);
                    mma16816(cS[mt][nt], ah[mt], blf[nt]);
                    mma16816(cS[mt][nt], al[mt], bhf[nt]);
                }
        }
        __syncthreads();   // Q/K reads done; Ssm may overwrite
        int rb = wm*32 + (lane >> 2);
        #pragma unroll
        for (int mt = 0; mt < 2; mt++)
            #pragma unroll
            for (int nt = 0; nt < 8; nt++)
                #pragma unroll
                for (int half = 0; half < 2; half++){
                    int row = rb + mt*16 + half*8;
                    int col = wn*64 + nt*8 + (lane & 3)*2;
                    float rv0 = cS[mt][nt][half*2+0], rv1 = cS[mt][nt][half*2+1];
                    atomicAdd(&mvs[(t0 + row - col) & (LL-1)], rv0);
                    atomicAdd(&mvs[(t0 + row - col - 1) & (LL-1)], rv1);
                    *(float2*)&Ssm[row*SPIT + col] =
                        make_float2(rv0*0.125f + msk[col], rv1*0.125f + msk[col+1]);
                }
    }
    __syncthreads();
    atomicAdd(&g_mv[b*LL + tid], mvs[tid]*(1.0f/DD));
    // ---- softmax rows (4 threads per row) ----
    {
        int r = tid >> 2, q = tid & 3;
        float* Srow = Ssm + r*SPIT + q*64;
        float mx = -1e30f;
        #pragma unroll 16
        for (int cc = 0; cc < 64; cc++) mx = fmaxf(mx, Srow[cc]);
        mx = fmaxf(mx, __shfl_xor_sync(0xffffffffu, mx, 1));
        mx = fmaxf(mx, __shfl_xor_sync(0xffffffffu, mx, 2));
        float sum = 0.f;
        #pragma unroll 16
        for (int cc = 0; cc < 64; cc++){
            float e = expf(Srow[cc] - mx);
            Srow[cc] = e;
            sum += e;
        }
        sum += __shfl_xor_sync(0xffffffffu, sum, 1);
        sum += __shfl_xor_sync(0xffffffffu, sum, 2);
        if (q == 0) invs[r] = 1.0f/sum;
    }
    // ---- phase 2: P @ Vt ----
    int wmP = warp & 3, wnP = warp >> 2;
    uint32_t sPh = s2u(Ph), sPl = s2u(Pl), sVh = s2u(Vh), sVl = s2u(Vl);
    float cP[4][4] = {};
    for (int s0 = 0; s0 < LL; s0 += 32){
        __syncthreads();
        {
            int r = tid >> 2, q = tid & 3;
            #pragma unroll
            for (int j = 0; j < 8; j++){
                int sl = q*8 + j;
                __nv_bfloat16 hi, lo; bfsplit(Ssm[r*SPIT + s0 + sl], hi, lo);
                Ph[r*PIT + sl] = hi; Pl[r*PIT + sl] = lo;
            }
        }
        {
            int e = tid & 63, sj = tid >> 6;
            #pragma unroll
            for (int j = 0; j < 8; j++){
                int sl = sj*8 + j;
                float v = g_qkvt[(size_t)(b*LL + s0 + sl)*384 + 256 + h*EE + e];
                __nv_bfloat16 hi, lo; bfsplit(v, hi, lo);
                Vh[e*PIT + sl] = hi; Vl[e*PIT + sl] = lo;
            }
        }
        __syncthreads();
        #pragma unroll
        for (int ks = 0; ks < 2; ks++){
            int kb = ks*16;
            uint32_t ah[4], al[4], bhf[4][2], blf[4][2];
            uint32_t offa = (uint32_t)((wmP*16 + a_row)*PIT + kb + a_koff)*2;
            ldm_x4(ah[0],ah[1],ah[2],ah[3], sPh + offa);
            ldm_x4(al[0],al[1],al[2],al[3], sPl + offa);
            #pragma unroll
            for (int np = 0; np < 2; np++){
                uint32_t off = (uint32_t)((wnP*32 + np*16 + b_nsel*8 + b_row)*PIT + kb + b_koff)*2;
                ldm_x4(bhf[2*np][0],bhf[2*np][1],bhf[2*np+1][0],bhf[2*np+1][1], sVh + off);
                ldm_x4(blf[2*np][0],blf[2*np][1],blf[2*np+1][0],blf[2*np+1][1], sVl + off);
            }
            #pragma unroll
            for (int nt = 0; nt < 4; nt++){
                mma16816(cP[nt], ah, bhf[nt]);
                mma16816(cP[nt], ah, blf[nt]);
                mma16816(cP[nt], al, bhf[nt]);
            }
        }
    }
    // ---- write spatial ----
    int rl = wmP*16 + (lane >> 2);
    #pragma unroll
    for (int nt = 0; nt < 4; nt++)
        #pragma unroll
        for (int half = 0; half < 2; half++){
            int row_l = rl + half*8;
            int t = t0 + row_l;
            float inv = invs[row_l];
            int col = wnP*32 + nt*8 + (lane & 3)*2;
            *(float2*)&g_sp[(size_t)(b*LL + t)*DD + h*EE + col] =
                make_float2(cP[nt][half*2+0]*inv, cP[nt][half*2+1]*inv);
        }
}

// ---------------- combine: ao = 0.9*freq + 0.1*spatial ----------------
__global__ void combine_k(){
    int bt = blockIdx.x; int b = bt >> 8; int t = bt & (LL-1);
    int d = threadIdx.x;
    int d5[KTOP]; float w5[KTOP];
    #pragma unroll
    for (int j = 0; j < KTOP; j++){ d5[j] = g_delays[j]; w5[j] = g_w[b*KTOP + j]; }
    float fr = 0.f;
    #pragma unroll
    for (int j = 0; j < KTOP; j++){
        int tt = (t + d5[j]) & (LL-1);
        fr += w5[j]*g_v[((size_t)b*LL + tt)*DD + d];
    }
    g_ao[(size_t)bt*DD + d] = 0.9f*fr + 0.1f*g_sp[(size_t)bt*DD + d];
}

// ---------------- weight transposes + split, one launch (both layers) ----------------
__global__ void transp_all(const float* __restrict__ Wq, const float* __restrict__ Wk,
                           const float* __restrict__ Wv, const float* __restrict__ Wp,
                           const float* __restrict__ F1, const float* __restrict__ F2){
    int j = blockIdx.x, layer = j/6, idx = j%6;
    const float* src; int K, N, doff;
    switch(idx){
        case 0: src = Wq + layer*16384; K=128; N=128; doff=0; break;
        case 1: src = Wk + layer*16384; K=128; N=128; doff=16384; break;
        case 2: src = Wv + layer*16384; K=128; N=128; doff=32768; break;
        case 3: src = Wp + layer*16384; K=128; N=128; doff=49152; break;
        case 4: src = F1 + layer*32768; K=128; N=256; doff=65536; break;
        default: src = F2 + layer*32768; K=256; N=128; doff=98304; break;
    }
    doff += layer*131072;
    int total = K*N;
    int kmask = K - 1, kshift = (K == 128) ? 7 : 8;
    for (int e = blockIdx.y*blockDim.x + threadIdx.x; e < total; e += gridDim.y*blockDim.x){
        int kk = e & kmask, n = e >> kshift;
        __nv_bfloat16 hi, lo;
        bfsplit(src[(size_t)kk*N + n], hi, lo);
        g_wTbh[doff + e] = hi;
        g_wTbl[doff + e] = lo;
    }
}

// ---------------- embedding ----------------
__global__ void embed_k(const int* __restrict__ paths,
                        const float* __restrict__ ego,
                        const float* __restrict__ pos){
    int bt = blockIdx.x; int t = bt & (LL-1); int d = threadIdx.x;
    int p = paths[bt];
    g_x[(size_t)bt*DD + d] = ego[(size_t)p*DD + d] + pos[t*DD + d];
}

// ---------------- band-pass impulse responses + split circulant matrices ----------------
__global__ void filt2_k(){
    int layer = blockIdx.x, n = threadIdx.x;
    const int lefts[2]  = {51, 0};
    const int rights[2] = {129, 78};
    int l = lefts[layer], r = rights[layer];
    double s = 0.0;
    for (int f = l; f < r; f++){
        double w = (f == 0 || f == LL/2) ? 1.0 : 2.0;
        s += w * cos(6.283185307179586477 * (double)(f*n) / (double)LL);
    }
    g_hf[layer*LL + n] = (float)(s / (double)LL);
}
__global__ void buildC2_k(){
    int layer = blockIdx.y, t = blockIdx.x, s = threadIdx.x;
    float v = g_hf[layer*LL + ((t - s) & (LL-1))];
    __nv_bfloat16 hi, lo; bfsplit(v, hi, lo);
    g_Cbh[layer*LL*LL + t*LL + s] = hi;
    g_Cbl[layer*LL*LL + t*LL + s] = lo;
}
__global__ void zero_mv_k(){
    g_mv[blockIdx.x*1024 + threadIdx.x] = 0.f;
}

// ---------------- top-5 delays + per-batch weights ----------------
__global__ void topk_k(){
    __shared__ float sc[LL];
    int tau = threadIdx.x;
    float a = 0.f;
    for (int b = 0; b < BB; b++) a += g_mv[b*LL + tau];
    sc[tau] = a * (1.0f/BB);
    __syncthreads();
    if (tau == 0){
        for (int j = 0; j < KTOP; j++){
            float best = -1e30f; int bi = 0;
            for (int i = 0; i < LL; i++) if (sc[i] > best){ best = sc[i]; bi = i; }
            g_delays[j] = bi;
            sc[bi] = -1e30f;
        }
    }
}
__global__ void weights_k(){
    int b = threadIdx.x;
    float v[KTOP]; float mx = -1e30f;
    #pragma unroll
    for (int j = 0; j < KTOP; j++){ v[j] = g_mv[b*LL + g_delays[j]]; mx = fmaxf(mx, v[j]); }
    float s = 0.f;
    #pragma unroll
    for (int j = 0; j < KTOP; j++){ v[j] = expf(v[j]-mx); s += v[j]; }
    #pragma unroll
    for (int j = 0; j < KTOP; j++) g_w[b*KTOP + j] = v[j]/s;
}

// ---------------- final gather ----------------
__global__ void gather_k(const int* __restrict__ lengths, float* __restrict__ out){
    int b = blockIdx.x, d = threadIdx.x;
    int t = lengths[b] - 1;
    out[b*DD + d] = g_x[((size_t)b*LL + t)*DD + d];
}

// =====================================================================
extern "C" void kernel_launch(void* const* d_in, const int* in_sizes, int n_in,
                              void* d_out, int out_size){
    (void)in_sizes; (void)n_in; (void)out_size;
    const int*   paths   = (const int*)  d_in[0];
    const int*   lengths = (const int*)  d_in[1];
    const float* ego     = (const float*)d_in[4];
    const float* pos     = (const float*)d_in[5];
    const float* Wq      = (const float*)d_in[6];
    const float* Wk      = (const float*)d_in[7];
    const float* Wv      = (const float*)d_in[8];
    const float* Wp      = (const float*)d_in[9];
    const float* F1      = (const float*)d_in[10];
    const float* F2      = (const float*)d_in[11];
    float* outp = (float*)d_out;

    static bool init_done = false;
    static float *px, *pxf, *pqkvt, *pv, *pao, *pa, *ph;
    static __nv_bfloat16 *pCbh, *pCbl, *pwTbh, *pwTbl;
    if (!init_done){
        cudaFuncSetAttribute(attn_tc, cudaFuncAttributeMaxDynamicSharedMemorySize, BSMEM);
        cudaGetSymbolAddress((void**)&px,   g_x);
        cudaGetSymbolAddress((void**)&pxf,  g_xf);
        cudaGetSymbolAddress((void**)&pqkvt,g_qkvt);
        cudaGetSymbolAddress((void**)&pv,   g_v);
        cudaGetSymbolAddress((void**)&pao,  g_ao);
        cudaGetSymbolAddress((void**)&pa,   g_a);
        cudaGetSymbolAddress((void**)&ph,   g_h);
        cudaGetSymbolAddress((void**)&pCbh, g_Cbh);
        cudaGetSymbolAddress((void**)&pCbl, g_Cbl);
        cudaGetSymbolAddress((void**)&pwTbh,g_wTbh);
        cudaGetSymbolAddress((void**)&pwTbl,g_wTbl);
        init_done = true;
    }

    embed_k<<<MROWS, DD>>>(paths, ego, pos);
    filt2_k<<<2, LL>>>();
    buildC2_k<<<dim3(LL,2), LL>>>();
    transp_all<<<dim3(12,8), 256>>>(Wq, Wk, Wv, Wp, F1, F2);

    for (int k = 0; k < 2; k++){
        __nv_bfloat16 *wh = pwTbh + (size_t)k*131072, *wl = pwTbl + (size_t)k*131072;
        // xf = C @ x  (A = pre-split C; B = x fp32 transposed load; per-batch)
        gemm_mma<1,1><<<dim3(2,2,BB), 256>>>(pCbh + (size_t)k*LL*LL, pCbl + (size_t)k*LL*LL, LL, 0,
                                             px, nullptr, DD, (long)LL*DD,
                                             pxf, DD, (long)LL*DD, nullptr, LL, 0);
        // qkvt = xf @ [Wq|Wk|Wv]  (B pre-split)
        gemm_mma<0,0><<<dim3(512,6,1), 256>>>(pxf, nullptr, DD, 0, wh, wl, DD, 0,
                                              pqkvt, 384, 0, nullptr, DD, 0);
        // v = x @ Wv
        gemm_mma<0,0><<<dim3(512,2,1), 256>>>(px, nullptr, DD, 0, wh + 32768, wl + 32768, DD, 0,
                                              pv, DD, 0, nullptr, DD, 0);
        zero_mv_k<<<64, 1024>>>();
        attn_tc<<<dim3(4, BB*HH), 256, BSMEM>>>(paths);       // S once + mv + softmax + P@Vt
        topk_k<<<1, LL>>>();
        weights_k<<<1, BB>>>();
        combine_k<<<MROWS, DD>>>();
        // a = ao @ Wp + x
        gemm_mma<0,0><<<dim3(512,2,1), 256>>>(pao, nullptr, DD, 0, wh + 49152, wl + 49152, DD, 0,
                                              pa, DD, 0, px, DD, 1);
        // h = gelu(a @ F1)
        gemm_mma<0,0><<<dim3(512,4,1), 256>>>(pa, nullptr, DD, 0, wh + 65536, wl + 65536, DD, 0,
                                              ph, 2*DD, 0, nullptr, DD, 2);
        // x = h @ F2
        gemm_mma<0,0><<<dim3(512,2,1), 256>>>(ph, nullptr, 2*DD, 0, wh + 98304, wl + 98304, 2*DD, 0,
                                              px, DD, 0, nullptr, 2*DD, 0);
    }
    gather_k<<<BB, DD>>>(lengths, outp);
}